// round 1
// baseline (speedup 1.0000x reference)
#include <cuda_runtime.h>
#include <cuda_bf16.h>
#include <math.h>
#include <math_constants.h>

#define NN 100000
#define F1 128      // in features / hidden concat size
#define H1 4        // heads layer1
#define C1 32       // per-head channels layer1
#define OUTC 10     // layer2 out channels
#define NG 128      // num graphs
#define NEG_SLOPE 0.2f

// ---------------- scratch (device globals; no allocation allowed) ----------------
__device__ float g_h1[NN * F1];     // h = x@W1, later overwritten with elu output of layer1
__device__ float g_acc1[NN * F1];   // sum of ex * h[src]
__device__ float g_as1[NN * H1];
__device__ float g_ad1[NN * H1];
__device__ float g_m1[NN * H1];
__device__ float g_den1[NN * H1];

__device__ float g_h2[NN * OUTC];
__device__ float g_acc2[NN * OUTC];
__device__ float g_as2[NN];
__device__ float g_ad2[NN];
__device__ float g_m2[NN];
__device__ float g_den2[NN];

__device__ float g_pool[NG * OUTC];
__device__ float g_cnt[NG];

// ---------------- helpers ----------------
__device__ __forceinline__ void atomicMaxFloat(float* addr, float val) {
    // works for mixed signs when initialized to -inf
    if (val >= 0.0f)
        atomicMax((int*)addr, __float_as_int(val));
    else
        atomicMin((unsigned int*)addr, __float_as_uint(val));
}

__device__ __forceinline__ float lrelu(float v) {
    return v > 0.0f ? v : NEG_SLOPE * v;
}

__device__ __forceinline__ float elu(float v) {
    return v > 0.0f ? v : expm1f(v);
}

// ---------------- init ----------------
__global__ void init_kernel() {
    int stride = gridDim.x * blockDim.x;
    for (int i = blockIdx.x * blockDim.x + threadIdx.x; i < NN * F1; i += stride) {
        g_acc1[i] = 0.0f;
        if (i < NN * OUTC) g_acc2[i] = 0.0f;
        if (i < NN * H1) { g_den1[i] = 0.0f; g_m1[i] = -CUDART_INF_F; }
        if (i < NN)      { g_den2[i] = 0.0f; g_m2[i] = -CUDART_INF_F; }
        if (i < NG * OUTC) g_pool[i] = 0.0f;
        if (i < NG)        g_cnt[i] = 0.0f;
    }
}

// ---------------- GEMM1: h1 = x @ W1   (N x 128) @ (128 x 128) ----------------
#define GROWS 64
__global__ void gemm1_kernel(const float* __restrict__ x, const float* __restrict__ W1) {
    extern __shared__ float smem[];
    float* Ws = smem;              // 128*128
    float* xs = smem + F1 * F1;    // GROWS*128
    int t = threadIdx.x;           // 128 threads
    for (int i = t; i < F1 * F1; i += 128) Ws[i] = W1[i];
    int row0 = blockIdx.x * GROWS;
    for (int i = t; i < GROWS * F1; i += 128) {
        int r = i >> 7, c = i & 127;
        int gr = row0 + r;
        xs[i] = (gr < NN) ? x[gr * F1 + c] : 0.0f;
    }
    __syncthreads();
    float acc[GROWS];
#pragma unroll
    for (int r = 0; r < GROWS; r++) acc[r] = 0.0f;
    for (int k = 0; k < F1; k++) {
        float w = Ws[k * F1 + t];
#pragma unroll
        for (int r = 0; r < GROWS; r++) acc[r] += xs[r * F1 + k] * w;
    }
#pragma unroll
    for (int r = 0; r < GROWS; r++) {
        int gr = row0 + r;
        if (gr < NN) g_h1[gr * F1 + t] = acc[r];
    }
}

// ---------------- attention coefficients layer1: warp per node ----------------
__global__ void att1_kernel(const float* __restrict__ att_s, const float* __restrict__ att_d) {
    int node = (blockIdx.x * blockDim.x + threadIdx.x) >> 5;
    int lane = threadIdx.x & 31;
    if (node >= NN) return;
    const float* hrow = &g_h1[node * F1];
    float s[H1], d[H1];
#pragma unroll
    for (int h = 0; h < H1; h++) {
        float v = hrow[h * C1 + lane];
        s[h] = v * att_s[h * C1 + lane];
        d[h] = v * att_d[h * C1 + lane];
    }
#pragma unroll
    for (int o = 16; o; o >>= 1) {
#pragma unroll
        for (int h = 0; h < H1; h++) {
            s[h] += __shfl_down_sync(0xffffffffu, s[h], o);
            d[h] += __shfl_down_sync(0xffffffffu, d[h], o);
        }
    }
    if (lane == 0) {
#pragma unroll
        for (int h = 0; h < H1; h++) {
            g_as1[node * H1 + h] = s[h];
            g_ad1[node * H1 + h] = d[h];
        }
    }
}

// ---------------- edge max pass (templated over H) ----------------
template <int H>
__global__ void edge_max_kernel(const int* __restrict__ ei, int E_real, int E_tot,
                                const float* __restrict__ as, const float* __restrict__ ad,
                                float* __restrict__ m) {
    int e = blockIdx.x * blockDim.x + threadIdx.x;
    if (e >= E_tot) return;
    int s, d;
    if (e < E_real) { s = ei[e]; d = ei[E_real + e]; }
    else            { s = d = e - E_real; }
#pragma unroll
    for (int h = 0; h < H; h++) {
        float v = lrelu(as[s * H + h] + ad[d * H + h]);
        atomicMaxFloat(&m[d * H + h], v);
    }
}

// ---------------- edge accumulate layer1: warp per edge ----------------
__global__ void edge_acc1_kernel(const int* __restrict__ ei, int E_real, int E_tot) {
    int e = (blockIdx.x * blockDim.x + threadIdx.x) >> 5;
    int lane = threadIdx.x & 31;
    if (e >= E_tot) return;
    int s, d;
    if (e < E_real) { s = ei[e]; d = ei[E_real + e]; }
    else            { s = d = e - E_real; }
    float ex = 0.0f;
    if (lane < H1) {
        float v = lrelu(g_as1[s * H1 + lane] + g_ad1[d * H1 + lane]);
        ex = expf(v - g_m1[d * H1 + lane]);
        atomicAdd(&g_den1[d * H1 + lane], ex);
    }
    float exh[H1];
#pragma unroll
    for (int h = 0; h < H1; h++) exh[h] = __shfl_sync(0xffffffffu, ex, h);
#pragma unroll
    for (int p = 0; p < H1; p++) {
        int j = p * C1 + lane;
        atomicAdd(&g_acc1[d * F1 + j], exh[p] * g_h1[s * F1 + j]);
    }
}

// ---------------- finalize layer1: h1 = elu(acc/den + b1) ----------------
__global__ void fin1_kernel(const float* __restrict__ b1) {
    int idx = blockIdx.x * blockDim.x + threadIdx.x;
    if (idx >= NN * F1) return;
    int j = idx & 127;
    int n = idx >> 7;
    int h = j >> 5;
    float v = g_acc1[idx] / (g_den1[n * H1 + h] + 1e-16f) + b1[j];
    g_h1[idx] = elu(v);
}

// ---------------- GEMM2 + attention layer2: warp per node ----------------
__global__ void gemm2att2_kernel(const float* __restrict__ W2,
                                 const float* __restrict__ att_s2,
                                 const float* __restrict__ att_d2) {
    __shared__ float W2s[F1 * OUTC];
    __shared__ float as2s[OUTC], ad2s[OUTC];
    int t = threadIdx.x;
    for (int i = t; i < F1 * OUTC; i += blockDim.x) W2s[i] = W2[i];
    if (t < OUTC) { as2s[t] = att_s2[t]; ad2s[t] = att_d2[t]; }
    __syncthreads();
    int node = (blockIdx.x * blockDim.x + t) >> 5;
    int lane = t & 31;
    if (node >= NN) return;
    float acc[OUTC];
#pragma unroll
    for (int c = 0; c < OUTC; c++) acc[c] = 0.0f;
#pragma unroll
    for (int kk = 0; kk < 4; kk++) {
        int k = kk * 32 + lane;
        float hv = g_h1[node * F1 + k];
#pragma unroll
        for (int c = 0; c < OUTC; c++) acc[c] += hv * W2s[k * OUTC + c];
    }
#pragma unroll
    for (int o = 16; o; o >>= 1)
#pragma unroll
        for (int c = 0; c < OUTC; c++) acc[c] += __shfl_xor_sync(0xffffffffu, acc[c], o);
    if (lane == 0) {
        float as = 0.0f, ad = 0.0f;
#pragma unroll
        for (int c = 0; c < OUTC; c++) {
            g_h2[node * OUTC + c] = acc[c];
            as += acc[c] * as2s[c];
            ad += acc[c] * ad2s[c];
        }
        g_as2[node] = as;
        g_ad2[node] = ad;
    }
}

// ---------------- edge accumulate layer2: thread per edge ----------------
__global__ void edge_acc2_kernel(const int* __restrict__ ei, int E_real, int E_tot) {
    int e = blockIdx.x * blockDim.x + threadIdx.x;
    if (e >= E_tot) return;
    int s, d;
    if (e < E_real) { s = ei[e]; d = ei[E_real + e]; }
    else            { s = d = e - E_real; }
    float v = lrelu(g_as2[s] + g_ad2[d]);
    float ex = expf(v - g_m2[d]);
    atomicAdd(&g_den2[d], ex);
#pragma unroll
    for (int c = 0; c < OUTC; c++)
        atomicAdd(&g_acc2[d * OUTC + c], ex * g_h2[s * OUTC + c]);
}

// ---------------- finalize layer2 + pooling ----------------
__global__ void fin2pool_kernel(const float* __restrict__ b2, const int* __restrict__ batch) {
    int n = blockIdx.x * blockDim.x + threadIdx.x;
    if (n >= NN) return;
    float den = g_den2[n] + 1e-16f;
    int g = batch[n];
#pragma unroll
    for (int c = 0; c < OUTC; c++) {
        float v = elu(g_acc2[n * OUTC + c] / den + b2[c]);
        atomicAdd(&g_pool[g * OUTC + c], v);
    }
    atomicAdd(&g_cnt[n < NN ? g : 0], 1.0f);
}

// ---------------- final: mean + log_softmax ----------------
__global__ void final_kernel(float* __restrict__ out) {
    int g = threadIdx.x;
    if (g >= NG) return;
    float cnt = fmaxf(g_cnt[g], 1.0f);
    float p[OUTC];
    float mx = -CUDART_INF_F;
#pragma unroll
    for (int c = 0; c < OUTC; c++) {
        p[c] = g_pool[g * OUTC + c] / cnt;
        mx = fmaxf(mx, p[c]);
    }
    float se = 0.0f;
#pragma unroll
    for (int c = 0; c < OUTC; c++) se += expf(p[c] - mx);
    float lse = mx + logf(se);
#pragma unroll
    for (int c = 0; c < OUTC; c++) out[g * OUTC + c] = p[c] - lse;
}

// ---------------- launch ----------------
extern "C" void kernel_launch(void* const* d_in, const int* in_sizes, int n_in,
                              void* d_out, int out_size) {
    const float* x       = (const float*)d_in[0];
    const float* W1      = (const float*)d_in[1];
    const float* att_s1  = (const float*)d_in[2];
    const float* att_d1  = (const float*)d_in[3];
    const float* b1      = (const float*)d_in[4];
    const float* W2      = (const float*)d_in[5];
    const float* att_s2  = (const float*)d_in[6];
    const float* att_d2  = (const float*)d_in[7];
    const float* b2      = (const float*)d_in[8];
    const int*   ei      = (const int*)d_in[9];
    const int*   batch   = (const int*)d_in[10];
    float* out = (float*)d_out;

    int E_real = in_sizes[9] / 2;
    int E_tot = E_real + NN;

    // init scratch
    init_kernel<<<2048, 256>>>();

    // layer 1
    int gemm1_smem = (F1 * F1 + GROWS * F1) * (int)sizeof(float);
    cudaFuncSetAttribute(gemm1_kernel, cudaFuncAttributeMaxDynamicSharedMemorySize, gemm1_smem);
    gemm1_kernel<<<(NN + GROWS - 1) / GROWS, 128, gemm1_smem>>>(x, W1);

    att1_kernel<<<(NN * 32 + 255) / 256, 256>>>(att_s1, att_d1);

    float* m1p; cudaGetSymbolAddress((void**)&m1p, g_m1);
    float* as1p; cudaGetSymbolAddress((void**)&as1p, g_as1);
    float* ad1p; cudaGetSymbolAddress((void**)&ad1p, g_ad1);
    edge_max_kernel<H1><<<(E_tot + 255) / 256, 256>>>(ei, E_real, E_tot, as1p, ad1p, m1p);

    edge_acc1_kernel<<<((long long)E_tot * 32 + 255) / 256, 256>>>(ei, E_real, E_tot);

    fin1_kernel<<<(NN * F1 + 255) / 256, 256>>>(b1);

    // layer 2
    gemm2att2_kernel<<<(NN * 32 + 255) / 256, 256>>>(W2, att_s2, att_d2);

    float* m2p; cudaGetSymbolAddress((void**)&m2p, g_m2);
    float* as2p; cudaGetSymbolAddress((void**)&as2p, g_as2);
    float* ad2p; cudaGetSymbolAddress((void**)&ad2p, g_ad2);
    edge_max_kernel<1><<<(E_tot + 255) / 256, 256>>>(ei, E_real, E_tot, as2p, ad2p, m2p);

    edge_acc2_kernel<<<(E_tot + 255) / 256, 256>>>(ei, E_real, E_tot);

    fin2pool_kernel<<<(NN + 255) / 256, 256>>>(b2, batch);

    final_kernel<<<1, NG>>>(out);
}

// round 2
// speedup vs baseline: 2.5558x; 2.5558x over previous
#include <cuda_runtime.h>
#include <cuda_bf16.h>
#include <math.h>
#include <math_constants.h>

#define NN 100000
#define F1 128
#define H1 4
#define C1 32
#define OUTC 10
#define OP 16        // padded layer2 channels
#define NG 128
#define NEG_SLOPE 0.2f

// ---------------- scratch ----------------
__device__ float4 g_h1[NN * 32];      // h = x@W1  (128 f32 per node)
__device__ float4 g_acc1[NN * 32];    // sum of ex * h[src]
__device__ float  g_as1[NN * H1];
__device__ float  g_ad1[NN * H1];
__device__ float  g_den1[NN * H1];

__device__ float4 g_h2p[NN * 4];      // layer2 features padded to 16
__device__ float4 g_acc2p[NN * 4];
__device__ float  g_as2[NN];
__device__ float  g_ad2[NN];
__device__ float  g_den2[NN];

__device__ float  g_pool[NG * OUTC];
__device__ float  g_cnt[NG];

// ---------------- helpers ----------------
__device__ __forceinline__ float lrelu(float v) { return v > 0.0f ? v : NEG_SLOPE * v; }
__device__ __forceinline__ float elu(float v)   { return v > 0.0f ? v : expm1f(v); }

__device__ __forceinline__ void red_add_v4(float4* addr, float4 v) {
    asm volatile("red.global.add.v4.f32 [%0], {%1,%2,%3,%4};"
                 :: "l"(addr), "f"(v.x), "f"(v.y), "f"(v.z), "f"(v.w) : "memory");
}

// ---------------- GEMM1: h1 = x @ W1  (100000x128 @ 128x128) ----------------
#define TM 64
__global__ void gemm1_kernel(const float* __restrict__ x, const float* __restrict__ W1) {
    extern __shared__ float smem[];
    float* Ws = smem;                 // 128*128
    float* xs = smem + F1 * F1;       // 64 rows * 132 (padded)
    float4* Wsv = (float4*)Ws;
    int t = threadIdx.x;              // 256 threads
    const float4* W1v = (const float4*)W1;
    for (int i = t; i < F1 * F1 / 4; i += 256) Wsv[i] = W1v[i];
    int row0 = blockIdx.x * TM;
    const float4* xv = (const float4*)x;
    for (int i = t; i < TM * 32; i += 256) {
        int r = i >> 5, c4 = i & 31;
        int gr = row0 + r;
        float4 v = (gr < NN) ? xv[gr * 32 + c4] : make_float4(0, 0, 0, 0);
        *(float4*)&xs[r * 132 + c4 * 4] = v;
    }
    __syncthreads();
    int tx = t & 31, ty = t >> 5;
    float acc[8][4];
#pragma unroll
    for (int r = 0; r < 8; r++)
#pragma unroll
        for (int c = 0; c < 4; c++) acc[r][c] = 0.0f;

#pragma unroll 4
    for (int k = 0; k < F1; k++) {
        float4 w = Wsv[k * 32 + tx];
        float xk[8];
#pragma unroll
        for (int r = 0; r < 8; r++) xk[r] = xs[(ty * 8 + r) * 132 + k];
#pragma unroll
        for (int r = 0; r < 8; r++) {
            acc[r][0] += xk[r] * w.x;
            acc[r][1] += xk[r] * w.y;
            acc[r][2] += xk[r] * w.z;
            acc[r][3] += xk[r] * w.w;
        }
    }
#pragma unroll
    for (int r = 0; r < 8; r++) {
        int gr = row0 + ty * 8 + r;
        if (gr < NN)
            g_h1[gr * 32 + tx] = make_float4(acc[r][0], acc[r][1], acc[r][2], acc[r][3]);
    }
}

// ---------------- attention coefficients layer1: warp per node ----------------
__global__ void att1_kernel(const float* __restrict__ att_s, const float* __restrict__ att_d) {
    int node = (blockIdx.x * blockDim.x + threadIdx.x) >> 5;
    int lane = threadIdx.x & 31;
    if (node >= NN) return;
    float4 v = g_h1[node * 32 + lane];
    float4 a = ((const float4*)att_s)[lane];
    float4 b = ((const float4*)att_d)[lane];
    float s = v.x * a.x + v.y * a.y + v.z * a.z + v.w * a.w;
    float d = v.x * b.x + v.y * b.y + v.z * b.z + v.w * b.w;
#pragma unroll
    for (int o = 1; o < 8; o <<= 1) {
        s += __shfl_xor_sync(0xffffffffu, s, o);
        d += __shfl_xor_sync(0xffffffffu, d, o);
    }
    if ((lane & 7) == 0) {
        g_as1[node * H1 + (lane >> 3)] = s;
        g_ad1[node * H1 + (lane >> 3)] = d;
    }
}

// ---------------- edge accumulate layer1: warp per edge (no max pass) ----------------
__global__ void edge_acc1_kernel(const int* __restrict__ ei, int E_real, int E_tot) {
    int e = (blockIdx.x * blockDim.x + threadIdx.x) >> 5;
    int lane = threadIdx.x & 31;
    if (e >= E_tot) return;
    int s, d;
    if (e < E_real) { s = __ldg(&ei[e]); d = __ldg(&ei[E_real + e]); }
    else            { s = d = e - E_real; }
    float ex = 0.0f;
    if (lane < H1) {
        float v = lrelu(g_as1[s * H1 + lane] + g_ad1[d * H1 + lane]);
        ex = __expf(v);
        atomicAdd(&g_den1[d * H1 + lane], ex);
    }
    float exl = __shfl_sync(0xffffffffu, ex, lane >> 3);   // head = lane/8
    float4 hv = g_h1[s * 32 + lane];
    float4 m = make_float4(hv.x * exl, hv.y * exl, hv.z * exl, hv.w * exl);
    red_add_v4(&g_acc1[d * 32 + lane], m);
}

// ---------------- layer2 node kernel: elu(acc1/den1+b1) -> @W2 -> att2 ----------------
__global__ void layer2_node_kernel(const float* __restrict__ W2,
                                   const float* __restrict__ att_s2,
                                   const float* __restrict__ att_d2,
                                   const float* __restrict__ b1) {
    __shared__ float W2s[F1 * OUTC];
    __shared__ float s_as[OUTC], s_ad[OUTC];
    int t = threadIdx.x;
    for (int i = t; i < F1 * OUTC; i += 256) W2s[i] = W2[i];
    if (t < OUTC) { s_as[t] = att_s2[t]; s_ad[t] = att_d2[t]; }
    __syncthreads();
    int node = (blockIdx.x * 256 + t) >> 5;
    int lane = t & 31;
    if (node >= NN) return;
    float den = g_den1[node * H1 + (lane >> 3)] + 1e-16f;
    float inv = 1.0f / den;
    float4 a = g_acc1[node * 32 + lane];
    float4 b = ((const float4*)b1)[lane];
    float h[4];
    h[0] = elu(a.x * inv + b.x);
    h[1] = elu(a.y * inv + b.y);
    h[2] = elu(a.z * inv + b.z);
    h[3] = elu(a.w * inv + b.w);
    float out[OUTC];
#pragma unroll
    for (int c = 0; c < OUTC; c++) out[c] = 0.0f;
#pragma unroll
    for (int i = 0; i < 4; i++) {
        int k = lane * 4 + i;
        float hk = h[i];
#pragma unroll
        for (int c = 0; c < OUTC; c++) out[c] += hk * W2s[k * OUTC + c];
    }
#pragma unroll
    for (int o = 16; o; o >>= 1)
#pragma unroll
        for (int c = 0; c < OUTC; c++) out[c] += __shfl_xor_sync(0xffffffffu, out[c], o);
    if (lane == 0) {
        float as = 0.0f, ad = 0.0f;
        float buf[OP];
#pragma unroll
        for (int c = 0; c < OUTC; c++) {
            buf[c] = out[c];
            as += out[c] * s_as[c];
            ad += out[c] * s_ad[c];
        }
#pragma unroll
        for (int c = OUTC; c < OP; c++) buf[c] = 0.0f;
#pragma unroll
        for (int j = 0; j < 4; j++)
            g_h2p[node * 4 + j] = make_float4(buf[j*4], buf[j*4+1], buf[j*4+2], buf[j*4+3]);
        g_as2[node] = as;
        g_ad2[node] = ad;
    }
}

// ---------------- edge accumulate layer2: 8 edges per warp, 4 lanes each ----------------
__global__ void edge_acc2_kernel(const int* __restrict__ ei, int E_real, int E_tot) {
    int warp = (blockIdx.x * blockDim.x + threadIdx.x) >> 5;
    int lane = threadIdx.x & 31;
    int sub = lane >> 2, li = lane & 3;
    int e = warp * 8 + sub;
    bool act = (e < E_tot);
    int s = 0, d = 0;
    if (act) {
        if (e < E_real) { s = __ldg(&ei[e]); d = __ldg(&ei[E_real + e]); }
        else            { s = d = e - E_real; }
    }
    float ex = 0.0f;
    if (act && li == 0) {
        float v = lrelu(g_as2[s] + g_ad2[d]);
        ex = __expf(v);
        atomicAdd(&g_den2[d], ex);
    }
    ex = __shfl_sync(0xffffffffu, ex, lane & ~3);
    if (act) {
        float4 hv = g_h2p[s * 4 + li];
        float4 m = make_float4(hv.x * ex, hv.y * ex, hv.z * ex, hv.w * ex);
        red_add_v4(&g_acc2p[d * 4 + li], m);
    }
}

// ---------------- finalize layer2 + pooling ----------------
__global__ void fin2pool_kernel(const float* __restrict__ b2, const int* __restrict__ batch) {
    int n = blockIdx.x * blockDim.x + threadIdx.x;
    if (n >= NN) return;
    float inv = 1.0f / (g_den2[n] + 1e-16f);
    int g = batch[n];
    const float* accr = (const float*)&g_acc2p[n * 4];
#pragma unroll
    for (int c = 0; c < OUTC; c++) {
        float v = elu(accr[c] * inv + b2[c]);
        atomicAdd(&g_pool[g * OUTC + c], v);
    }
    atomicAdd(&g_cnt[g], 1.0f);
}

// ---------------- final: mean + log_softmax ----------------
__global__ void final_kernel(float* __restrict__ out) {
    int g = threadIdx.x;
    if (g >= NG) return;
    float cnt = fmaxf(g_cnt[g], 1.0f);
    float p[OUTC];
    float mx = -CUDART_INF_F;
#pragma unroll
    for (int c = 0; c < OUTC; c++) {
        p[c] = g_pool[g * OUTC + c] / cnt;
        mx = fmaxf(mx, p[c]);
    }
    float se = 0.0f;
#pragma unroll
    for (int c = 0; c < OUTC; c++) se += expf(p[c] - mx);
    float lse = mx + logf(se);
#pragma unroll
    for (int c = 0; c < OUTC; c++) out[g * OUTC + c] = p[c] - lse;
}

// ---------------- launch ----------------
extern "C" void kernel_launch(void* const* d_in, const int* in_sizes, int n_in,
                              void* d_out, int out_size) {
    const float* x      = (const float*)d_in[0];
    const float* W1     = (const float*)d_in[1];
    const float* att_s1 = (const float*)d_in[2];
    const float* att_d1 = (const float*)d_in[3];
    const float* b1     = (const float*)d_in[4];
    const float* W2     = (const float*)d_in[5];
    const float* att_s2 = (const float*)d_in[6];
    const float* att_d2 = (const float*)d_in[7];
    const float* b2     = (const float*)d_in[8];
    const int*   ei     = (const int*)d_in[9];
    const int*   batch  = (const int*)d_in[10];
    float* out = (float*)d_out;

    int E_real = in_sizes[9] / 2;
    int E_tot = E_real + NN;

    void *p_acc1, *p_den1, *p_acc2, *p_den2, *p_pool, *p_cnt;
    cudaGetSymbolAddress(&p_acc1, g_acc1);
    cudaGetSymbolAddress(&p_den1, g_den1);
    cudaGetSymbolAddress(&p_acc2, g_acc2p);
    cudaGetSymbolAddress(&p_den2, g_den2);
    cudaGetSymbolAddress(&p_pool, g_pool);
    cudaGetSymbolAddress(&p_cnt,  g_cnt);

    cudaMemsetAsync(p_acc1, 0, (size_t)NN * F1 * sizeof(float));
    cudaMemsetAsync(p_den1, 0, (size_t)NN * H1 * sizeof(float));
    cudaMemsetAsync(p_acc2, 0, (size_t)NN * OP * sizeof(float));
    cudaMemsetAsync(p_den2, 0, (size_t)NN * sizeof(float));
    cudaMemsetAsync(p_pool, 0, (size_t)NG * OUTC * sizeof(float));
    cudaMemsetAsync(p_cnt,  0, (size_t)NG * sizeof(float));

    int gemm1_smem = (F1 * F1 + TM * 132) * (int)sizeof(float);
    cudaFuncSetAttribute(gemm1_kernel, cudaFuncAttributeMaxDynamicSharedMemorySize, gemm1_smem);
    gemm1_kernel<<<(NN + TM - 1) / TM, 256, gemm1_smem>>>(x, W1);

    att1_kernel<<<(NN * 32 + 255) / 256, 256>>>(att_s1, att_d1);

    long long th1 = (long long)E_tot * 32;
    edge_acc1_kernel<<<(int)((th1 + 255) / 256), 256>>>(ei, E_real, E_tot);

    layer2_node_kernel<<<(NN * 32 + 255) / 256, 256>>>(W2, att_s2, att_d2, b1);

    long long warps2 = (E_tot + 7) / 8;
    long long th2 = warps2 * 32;
    edge_acc2_kernel<<<(int)((th2 + 255) / 256), 256>>>(ei, E_real, E_tot);

    fin2pool_kernel<<<(NN + 255) / 256, 256>>>(b2, batch);

    final_kernel<<<1, NG>>>(out);
}

// round 3
// speedup vs baseline: 3.6849x; 1.4418x over previous
#include <cuda_runtime.h>
#include <cuda_fp16.h>
#include <math.h>
#include <math_constants.h>

#define NN 100000
#define F1 128
#define H1 4
#define OUTC 10
#define OP 16
#define NG 128
#define NEG_SLOPE 0.2f

// ---------------- scratch ----------------
__device__ __align__(16) __half g_h1h[NN * F1];    // layer1 features, fp16
__device__ __align__(16) __half g_acc1h[NN * F1];  // fp16 atomic accumulator
__device__ __align__(16) float  g_as1[NN * H1];
__device__ __align__(16) float  g_ad1[NN * H1];
__device__ __align__(16) float  g_den1[NN * H1];

__device__ __align__(16) __half g_h2ph[NN * OP];
__device__ __align__(16) __half g_acc2ph[NN * OP];
__device__ float g_as2[NN];
__device__ float g_ad2[NN];
__device__ float g_den2[NN];

__device__ float g_pool[NG * OUTC];
__device__ float g_cnt[NG];

// ---------------- helpers ----------------
__device__ __forceinline__ float lrelu(float v) { return v > 0.0f ? v : NEG_SLOPE * v; }
__device__ __forceinline__ float elu(float v)   { return v > 0.0f ? v : expm1f(v); }

__device__ __forceinline__ unsigned long long pack2(float lo, float hi) {
    unsigned long long r;
    asm("mov.b64 %0, {%1, %2};" : "=l"(r) : "f"(lo), "f"(hi));
    return r;
}
__device__ __forceinline__ void unpack2(float& lo, float& hi, unsigned long long v) {
    asm("mov.b64 {%0, %1}, %2;" : "=f"(lo), "=f"(hi) : "l"(v));
}
__device__ __forceinline__ void fma2(unsigned long long& d, unsigned long long a, unsigned long long b) {
    asm("fma.rn.f32x2 %0, %1, %2, %0;" : "+l"(d) : "l"(a), "l"(b));
}

// ---------------- GEMM1 + fused attention dots ----------------
#define TM 64
__global__ void gemm1_att_kernel(const float* __restrict__ x, const float* __restrict__ W1,
                                 const float* __restrict__ att_s, const float* __restrict__ att_d) {
    extern __shared__ float smem[];
    float* Ws = smem;               // 128*128
    float* xs = smem + F1 * F1;     // 64*132
    float4* Wsv = (float4*)Ws;
    int t = threadIdx.x;            // 256 threads
    const float4* W1v = (const float4*)W1;
    for (int i = t; i < F1 * F1 / 4; i += 256) Wsv[i] = W1v[i];
    int row0 = blockIdx.x * TM;
    const float4* xv = (const float4*)x;
    for (int i = t; i < TM * 32; i += 256) {
        int r = i >> 5, c4 = i & 31;
        int gr = row0 + r;
        float4 v = (gr < NN) ? xv[gr * 32 + c4] : make_float4(0, 0, 0, 0);
        *(float4*)&xs[r * 132 + c4 * 4] = v;
    }
    __syncthreads();
    int tx = t & 31, ty = t >> 5;
    unsigned long long acc[8][2];
#pragma unroll
    for (int r = 0; r < 8; r++) { acc[r][0] = 0ULL; acc[r][1] = 0ULL; }

#pragma unroll 4
    for (int k = 0; k < F1; k++) {
        float4 w = Wsv[k * 32 + tx];
        unsigned long long w01 = pack2(w.x, w.y);
        unsigned long long w23 = pack2(w.z, w.w);
#pragma unroll
        for (int r = 0; r < 8; r++) {
            float xk = xs[(ty * 8 + r) * 132 + k];
            unsigned long long x2 = pack2(xk, xk);
            fma2(acc[r][0], x2, w01);
            fma2(acc[r][1], x2, w23);
        }
    }

    float4 as4 = ((const float4*)att_s)[tx];
    float4 ad4 = ((const float4*)att_d)[tx];
#pragma unroll
    for (int r = 0; r < 8; r++) {
        int gr = row0 + ty * 8 + r;
        float a0, a1, a2, a3;
        unpack2(a0, a1, acc[r][0]);
        unpack2(a2, a3, acc[r][1]);
        if (gr < NN) {
            __half2 p0 = __floats2half2_rn(a0, a1);
            __half2 p1 = __floats2half2_rn(a2, a3);
            __half2* hp = (__half2*)&g_h1h[gr * F1 + tx * 4];
            hp[0] = p0; hp[1] = p1;
        }
        float sp = a0 * as4.x + a1 * as4.y + a2 * as4.z + a3 * as4.w;
        float dp = a0 * ad4.x + a1 * ad4.y + a2 * ad4.z + a3 * ad4.w;
#pragma unroll
        for (int o = 1; o < 8; o <<= 1) {
            sp += __shfl_xor_sync(0xffffffffu, sp, o);
            dp += __shfl_xor_sync(0xffffffffu, dp, o);
        }
        if ((tx & 7) == 0 && gr < NN) {
            g_as1[gr * H1 + (tx >> 3)] = sp;
            g_ad1[gr * H1 + (tx >> 3)] = dp;
        }
    }
}

// ---------------- edge accumulate layer1: 16 lanes per edge, fp16 ----------------
__global__ void edge_acc1_kernel(const int* __restrict__ ei, int E_real, int E_tot) {
    int gtid = blockIdx.x * blockDim.x + threadIdx.x;
    int e = gtid >> 4;
    int sl = threadIdx.x & 15;
    int wl = threadIdx.x & 31;
    if (e >= E_tot) return;
    int s, d;
    if (e < E_real) { s = __ldg(&ei[e]); d = __ldg(&ei[E_real + e]); }
    else            { s = d = e - E_real; }
    float ex = 0.0f;
    if (sl < H1) {
        float v = lrelu(g_as1[s * H1 + sl] + g_ad1[d * H1 + sl]);
        ex = __expf(v);
        atomicAdd(&g_den1[d * H1 + sl], ex);
    }
    // head of this lane's 8 channels: sl>>2
    float exl = __shfl_sync(0xffffffffu, ex, (wl & 16) + (sl >> 2));
    __half2 ex2 = __float2half2_rn(exl);
    uint4 raw = *(const uint4*)&g_h1h[s * F1 + sl * 8];
    __half2 m0 = __hmul2(*(__half2*)&raw.x, ex2);
    __half2 m1 = __hmul2(*(__half2*)&raw.y, ex2);
    __half2 m2 = __hmul2(*(__half2*)&raw.z, ex2);
    __half2 m3 = __hmul2(*(__half2*)&raw.w, ex2);
    __half* dst = &g_acc1h[d * F1 + sl * 8];
    asm volatile("red.global.add.noftz.v4.f16x2 [%0], {%1,%2,%3,%4};"
                 :: "l"(dst), "r"(*(unsigned*)&m0), "r"(*(unsigned*)&m1),
                    "r"(*(unsigned*)&m2), "r"(*(unsigned*)&m3) : "memory");
}

// ---------------- layer2 node kernel ----------------
__global__ void layer2_node_kernel(const float* __restrict__ W2,
                                   const float* __restrict__ att_s2,
                                   const float* __restrict__ att_d2,
                                   const float* __restrict__ b1) {
    __shared__ float W2s[F1 * 11];   // padded stride 11 -> conflict-free
    __shared__ float s_as[OUTC], s_ad[OUTC];
    int t = threadIdx.x;
    for (int i = t; i < F1 * OUTC; i += 256) W2s[(i / OUTC) * 11 + (i % OUTC)] = W2[i];
    if (t < OUTC) { s_as[t] = att_s2[t]; s_ad[t] = att_d2[t]; }
    __syncthreads();
    int node = (blockIdx.x * 256 + t) >> 5;
    int lane = t & 31;
    if (node >= NN) return;
    float4 den4 = *(const float4*)&g_den1[node * H1];
    float inv[4] = { 1.0f / (den4.x + 1e-16f), 1.0f / (den4.y + 1e-16f),
                     1.0f / (den4.z + 1e-16f), 1.0f / (den4.w + 1e-16f) };
    float out[OUTC];
#pragma unroll
    for (int c = 0; c < OUTC; c++) out[c] = 0.0f;
#pragma unroll
    for (int i = 0; i < 4; i++) {
        int ch = lane + 32 * i;        // head == i
        float a = __half2float(g_acc1h[node * F1 + ch]);
        float h = elu(a * inv[i] + __ldg(&b1[ch]));
        const float* wr = &W2s[ch * 11];
#pragma unroll
        for (int c = 0; c < OUTC; c++) out[c] += h * wr[c];
    }
#pragma unroll
    for (int o = 16; o; o >>= 1)
#pragma unroll
        for (int c = 0; c < OUTC; c++) out[c] += __shfl_xor_sync(0xffffffffu, out[c], o);
    if (lane < 8) {
        float lo = 0.0f, hi = 0.0f;
        if (lane < 5) { lo = out[2 * lane]; hi = out[2 * lane + 1]; }
        ((__half2*)&g_h2ph[node * OP])[lane] = __floats2half2_rn(lo, hi);
    }
    if (lane == 0) {
        float as = 0.0f, ad = 0.0f;
#pragma unroll
        for (int c = 0; c < OUTC; c++) { as += out[c] * s_as[c]; ad += out[c] * s_ad[c]; }
        g_as2[node] = as;
        g_ad2[node] = ad;
    }
}

// ---------------- edge accumulate layer2: 4 lanes per edge, fp16 ----------------
__global__ void edge_acc2_kernel(const int* __restrict__ ei, int E_real, int E_tot) {
    int gtid = blockIdx.x * blockDim.x + threadIdx.x;
    int e = gtid >> 2;
    int li = threadIdx.x & 3;
    int wl = threadIdx.x & 31;
    if (e >= E_tot) return;
    int s, d;
    if (e < E_real) { s = __ldg(&ei[e]); d = __ldg(&ei[E_real + e]); }
    else            { s = d = e - E_real; }
    float ex = 0.0f;
    if (li == 0) {
        float v = lrelu(g_as2[s] + g_ad2[d]);
        ex = __expf(v);
        atomicAdd(&g_den2[d], ex);
    }
    float exl = __shfl_sync(0xffffffffu, ex, wl & ~3);
    __half2 ex2 = __float2half2_rn(exl);
    uint2 raw = *(const uint2*)&g_h2ph[s * OP + li * 4];
    __half2 m0 = __hmul2(*(__half2*)&raw.x, ex2);
    __half2 m1 = __hmul2(*(__half2*)&raw.y, ex2);
    __half* dst = &g_acc2ph[d * OP + li * 4];
    asm volatile("red.global.add.noftz.v2.f16x2 [%0], {%1,%2};"
                 :: "l"(dst), "r"(*(unsigned*)&m0), "r"(*(unsigned*)&m1) : "memory");
}

// ---------------- finalize layer2 + pooling ----------------
__global__ void fin2pool_kernel(const float* __restrict__ b2, const int* __restrict__ batch) {
    int n = blockIdx.x * blockDim.x + threadIdx.x;
    if (n >= NN) return;
    float inv = 1.0f / (g_den2[n] + 1e-16f);
    int g = batch[n];
#pragma unroll
    for (int c = 0; c < OUTC; c++) {
        float v = elu(__half2float(g_acc2ph[n * OP + c]) * inv + b2[c]);
        atomicAdd(&g_pool[g * OUTC + c], v);
    }
    atomicAdd(&g_cnt[g], 1.0f);
}

// ---------------- final: mean + log_softmax ----------------
__global__ void final_kernel(float* __restrict__ out) {
    int g = threadIdx.x;
    if (g >= NG) return;
    float cnt = fmaxf(g_cnt[g], 1.0f);
    float p[OUTC];
    float mx = -CUDART_INF_F;
#pragma unroll
    for (int c = 0; c < OUTC; c++) {
        p[c] = g_pool[g * OUTC + c] / cnt;
        mx = fmaxf(mx, p[c]);
    }
    float se = 0.0f;
#pragma unroll
    for (int c = 0; c < OUTC; c++) se += expf(p[c] - mx);
    float lse = mx + logf(se);
#pragma unroll
    for (int c = 0; c < OUTC; c++) out[g * OUTC + c] = p[c] - lse;
}

// ---------------- launch ----------------
extern "C" void kernel_launch(void* const* d_in, const int* in_sizes, int n_in,
                              void* d_out, int out_size) {
    const float* x      = (const float*)d_in[0];
    const float* W1     = (const float*)d_in[1];
    const float* att_s1 = (const float*)d_in[2];
    const float* att_d1 = (const float*)d_in[3];
    const float* b1     = (const float*)d_in[4];
    const float* W2     = (const float*)d_in[5];
    const float* att_s2 = (const float*)d_in[6];
    const float* att_d2 = (const float*)d_in[7];
    const float* b2     = (const float*)d_in[8];
    const int*   ei     = (const int*)d_in[9];
    const int*   batch  = (const int*)d_in[10];
    float* out = (float*)d_out;

    int E_real = in_sizes[9] / 2;
    int E_tot = E_real + NN;

    void *p_acc1, *p_den1, *p_acc2, *p_den2, *p_pool, *p_cnt;
    cudaGetSymbolAddress(&p_acc1, g_acc1h);
    cudaGetSymbolAddress(&p_den1, g_den1);
    cudaGetSymbolAddress(&p_acc2, g_acc2ph);
    cudaGetSymbolAddress(&p_den2, g_den2);
    cudaGetSymbolAddress(&p_pool, g_pool);
    cudaGetSymbolAddress(&p_cnt,  g_cnt);

    cudaMemsetAsync(p_acc1, 0, (size_t)NN * F1 * sizeof(__half));
    cudaMemsetAsync(p_den1, 0, (size_t)NN * H1 * sizeof(float));
    cudaMemsetAsync(p_acc2, 0, (size_t)NN * OP * sizeof(__half));
    cudaMemsetAsync(p_den2, 0, (size_t)NN * sizeof(float));
    cudaMemsetAsync(p_pool, 0, (size_t)NG * OUTC * sizeof(float));
    cudaMemsetAsync(p_cnt,  0, (size_t)NG * sizeof(float));

    int gemm1_smem = (F1 * F1 + TM * 132) * (int)sizeof(float);
    cudaFuncSetAttribute(gemm1_att_kernel, cudaFuncAttributeMaxDynamicSharedMemorySize, gemm1_smem);
    gemm1_att_kernel<<<(NN + TM - 1) / TM, 256, gemm1_smem>>>(x, W1, att_s1, att_d1);

    long long th1 = (long long)E_tot * 16;
    edge_acc1_kernel<<<(int)((th1 + 255) / 256), 256>>>(ei, E_real, E_tot);

    layer2_node_kernel<<<(NN * 32 + 255) / 256, 256>>>(W2, att_s2, att_d2, b1);

    long long th2 = (long long)E_tot * 4;
    edge_acc2_kernel<<<(int)((th2 + 255) / 256), 256>>>(ei, E_real, E_tot);

    fin2pool_kernel<<<(NN + 255) / 256, 256>>>(b2, batch);

    final_kernel<<<1, NG>>>(out);
}